// round 2
// baseline (speedup 1.0000x reference)
#include <cuda_runtime.h>

#define Nn 100000
#define Ee 1600000
#define Hh 64
#define Cc 10
#define Gg 64

// ---------------- static device scratch (no allocations allowed) ----------------
__device__ int   d_counts[Nn];          // in-degree (excl. self loop)
__device__ int   d_cursor[Nn];          // placement cursors
__device__ int   d_start[Nn];           // CSR row start (permuted order, irrelevant)
__device__ float d_dinv[Nn];            // rsqrt(1 + indeg)
__device__ int   d_sorted[Ee];          // src node id grouped by tgt
__device__ float d_g[Nn * Hh];          // GEMM output: dinv[row] * (u @ W)
__device__ float d_h[Nn * Hh];          // aggregation output: dinv[t] * sum
__device__ float d_psum[Gg * Hh];       // pooled sums
__device__ float d_pcnt[Gg];            // per-graph node counts
__device__ int   d_gcnt;                // global offset counter

// ---------------- prep kernels ----------------
__global__ void k_zero() {
    int i = blockIdx.x * blockDim.x + threadIdx.x;
    if (i < Nn) { d_counts[i] = 0; d_cursor[i] = 0; }
    if (i < Gg * Hh) d_psum[i] = 0.0f;
    if (i < Gg) d_pcnt[i] = 0.0f;
    if (i == 0) d_gcnt = 0;
}

__global__ void k_count(const int* __restrict__ tgt) {
    int e = blockIdx.x * blockDim.x + threadIdx.x;
    if (e >= Ee) return;
    int t = tgt[e];
    if ((unsigned)t < (unsigned)Nn) atomicAdd(&d_counts[t], 1);
}

// Block-aggregated offset allocation: start[i] = global_base + exclusive_prefix(counts)
// Row order across blocks is arbitrary (atomic base) — fine, CSR rows are independent.
__global__ void k_start() {
    int tid = threadIdx.x;
    int i = blockIdx.x * 1024 + tid;
    int v = (i < Nn) ? d_counts[i] : 0;
    int lane = tid & 31, wid = tid >> 5;
    int x = v;
#pragma unroll
    for (int d = 1; d < 32; d <<= 1) {
        int t = __shfl_up_sync(0xffffffffu, x, d);
        if (lane >= d) x += t;
    }
    __shared__ int ws[32];
    __shared__ int sbase;
    if (lane == 31) ws[wid] = x;
    __syncthreads();
    if (wid == 0) {
        int y = ws[lane];
#pragma unroll
        for (int d = 1; d < 32; d <<= 1) {
            int t = __shfl_up_sync(0xffffffffu, y, d);
            if (lane >= d) y += t;
        }
        ws[lane] = y;
    }
    __syncthreads();
    if (tid == 0) sbase = atomicAdd(&d_gcnt, ws[31]);
    __syncthreads();
    int excl = x - v + (wid ? ws[wid - 1] : 0);
    if (i < Nn) {
        d_start[i] = sbase + excl;
        d_dinv[i]  = rsqrtf(1.0f + (float)v);
    }
}

__global__ void k_fill(const int* __restrict__ src, const int* __restrict__ tgt) {
    int e = blockIdx.x * blockDim.x + threadIdx.x;
    if (e >= Ee) return;
    int t = tgt[e];
    int s = src[e];
    if ((unsigned)t >= (unsigned)Nn || (unsigned)s >= (unsigned)Nn) return;
    int pos = d_start[t] + atomicAdd(&d_cursor[t], 1);
    d_sorted[pos] = s;
}

// ---------------- fused GEMM: g[row] = dinv[row] * (pre(in[row]) @ W) ----------------
// PRE=false: in = x (external).  PRE=true: in = d_h, pre(v) = relu(v + bprev).
template <bool PRE>
__global__ void __launch_bounds__(256) k_gemm(const float* __restrict__ xin,
                                              const float* __restrict__ W,
                                              const float* __restrict__ bprev) {
    __shared__ float Ws[64][64];
    __shared__ float inT[64][68];   // transposed tile, stride 68 (16B-aligned, no conflicts)
    int tid = threadIdx.x;
    int row0 = blockIdx.x * 64;
    const float* in = PRE ? d_h : xin;

#pragma unroll
    for (int p = 0; p < 4; p++) {
        int f = tid + p * 256;
        int k = f >> 4, j = f & 15;
        float4 w = *(const float4*)&W[k * 64 + 4 * j];
        *(float4*)&Ws[k][4 * j] = w;
    }
#pragma unroll
    for (int p = 0; p < 4; p++) {
        int f = tid + p * 256;
        int r = f >> 4, j = f & 15;
        int row = row0 + r;
        float4 v = make_float4(0.f, 0.f, 0.f, 0.f);
        if (row < Nn) v = *(const float4*)&in[row * 64 + 4 * j];
        if (PRE) {
            v.x = fmaxf(v.x + bprev[4 * j + 0], 0.f);
            v.y = fmaxf(v.y + bprev[4 * j + 1], 0.f);
            v.z = fmaxf(v.z + bprev[4 * j + 2], 0.f);
            v.w = fmaxf(v.w + bprev[4 * j + 3], 0.f);
        }
        inT[4 * j + 0][r] = v.x;
        inT[4 * j + 1][r] = v.y;
        inT[4 * j + 2][r] = v.z;
        inT[4 * j + 3][r] = v.w;
    }
    __syncthreads();

    int ty = tid >> 4, tx = tid & 15;
    float acc[4][4] = {};
#pragma unroll 8
    for (int k = 0; k < 64; k++) {
        float4 a = *(float4*)&inT[k][4 * ty];
        float4 b = *(float4*)&Ws[k][4 * tx];
        float av[4] = {a.x, a.y, a.z, a.w};
        float bv[4] = {b.x, b.y, b.z, b.w};
#pragma unroll
        for (int i = 0; i < 4; i++)
#pragma unroll
            for (int j = 0; j < 4; j++)
                acc[i][j] = fmaf(av[i], bv[j], acc[i][j]);
    }
#pragma unroll
    for (int i = 0; i < 4; i++) {
        int row = row0 + 4 * ty + i;
        if (row < Nn) {
            float dv = d_dinv[row];
            float4 o = make_float4(acc[i][0] * dv, acc[i][1] * dv,
                                   acc[i][2] * dv, acc[i][3] * dv);
            *(float4*)&d_g[row * 64 + 4 * tx] = o;
        }
    }
}

// ---------------- aggregation: d_h[t] = dinv[t] * (g[t] + sum_{s in N(t)} g[s]) ----------------
// 16-lane group per node, one float4 per lane, unrolled x4 for MLP into L2.
__global__ void __launch_bounds__(256) k_agg() {
    int gid  = (blockIdx.x * blockDim.x + threadIdx.x) >> 4;
    int lane = threadIdx.x & 15;
    if (gid >= Nn) return;
    int t = gid;
    int base = d_start[t];
    int cnt  = d_counts[t];
    const float* __restrict__ g = d_g;
    float4 acc = *(const float4*)&g[t * 64 + 4 * lane];  // self loop
    int i = 0;
    for (; i + 4 <= cnt; i += 4) {
        int s0 = d_sorted[base + i + 0];
        int s1 = d_sorted[base + i + 1];
        int s2 = d_sorted[base + i + 2];
        int s3 = d_sorted[base + i + 3];
        float4 a = *(const float4*)&g[s0 * 64 + 4 * lane];
        float4 b = *(const float4*)&g[s1 * 64 + 4 * lane];
        float4 c = *(const float4*)&g[s2 * 64 + 4 * lane];
        float4 d = *(const float4*)&g[s3 * 64 + 4 * lane];
        acc.x += a.x + b.x + c.x + d.x;
        acc.y += a.y + b.y + c.y + d.y;
        acc.z += a.z + b.z + c.z + d.z;
        acc.w += a.w + b.w + c.w + d.w;
    }
    for (; i < cnt; i++) {
        int s = d_sorted[base + i];
        float4 a = *(const float4*)&g[s * 64 + 4 * lane];
        acc.x += a.x; acc.y += a.y; acc.z += a.z; acc.w += a.w;
    }
    float dv = d_dinv[t];
    float4 o = make_float4(acc.x * dv, acc.y * dv, acc.z * dv, acc.w * dv);
    *(float4*)&d_h[t * 64 + 4 * lane] = o;
}

// ---------------- mean pool (batch is sorted; run-accumulate, flush on graph change) ----------------
__global__ void __launch_bounds__(256) k_pool(const int* __restrict__ batch) {
    int ngroups = gridDim.x * (blockDim.x >> 4);
    int gid  = (blockIdx.x * blockDim.x + threadIdx.x) >> 4;
    int lane = threadIdx.x & 15;
    int chunk = (Nn + ngroups - 1) / ngroups;
    int lo = gid * chunk;
    int hi = min(lo + chunk, Nn);
    float4 acc = make_float4(0.f, 0.f, 0.f, 0.f);
    int cur = -1, rc = 0;
    for (int n = lo; n < hi; n++) {
        int bg = batch[n];
        if (bg != cur) {
            if (cur >= 0) {
                atomicAdd(&d_psum[cur * 64 + 4 * lane + 0], acc.x);
                atomicAdd(&d_psum[cur * 64 + 4 * lane + 1], acc.y);
                atomicAdd(&d_psum[cur * 64 + 4 * lane + 2], acc.z);
                atomicAdd(&d_psum[cur * 64 + 4 * lane + 3], acc.w);
                if (lane == 0) atomicAdd(&d_pcnt[cur], (float)rc);
            }
            cur = bg; acc = make_float4(0.f, 0.f, 0.f, 0.f); rc = 0;
        }
        float4 v = *(const float4*)&d_h[n * 64 + 4 * lane];
        acc.x += v.x; acc.y += v.y; acc.z += v.z; acc.w += v.w;
        rc++;
    }
    if (cur >= 0) {
        atomicAdd(&d_psum[cur * 64 + 4 * lane + 0], acc.x);
        atomicAdd(&d_psum[cur * 64 + 4 * lane + 1], acc.y);
        atomicAdd(&d_psum[cur * 64 + 4 * lane + 2], acc.z);
        atomicAdd(&d_psum[cur * 64 + 4 * lane + 3], acc.w);
        if (lane == 0) atomicAdd(&d_pcnt[cur], (float)rc);
    }
}

// ---------------- head: out[g,c] = (psum[g]/cnt[g] + b4) @ Wl + bl ----------------
__global__ void k_final(const float* __restrict__ Wl, const float* __restrict__ bl,
                        const float* __restrict__ b4, float* __restrict__ out) {
    int tid = threadIdx.x;
    if (tid >= Gg * Cc) return;
    int gi = tid / Cc, c = tid % Cc;
    float inv = 1.0f / fmaxf(d_pcnt[gi], 1.0f);
    float acc = bl[c];
#pragma unroll 8
    for (int k = 0; k < 64; k++) {
        float pooled = d_psum[gi * 64 + k] * inv + b4[k];
        acc = fmaf(pooled, Wl[k * Cc + c], acc);
    }
    out[gi * Cc + c] = acc;
}

// ---------------- launch ----------------
extern "C" void kernel_launch(void* const* d_in, const int* in_sizes, int n_in,
                              void* d_out, int out_size) {
    const float* x     = (const float*)d_in[0];
    const int*   ei    = (const int*)d_in[1];     // int32! (JAX x64 disabled)
    const int*   batch = (const int*)d_in[2];
    const float* W1 = (const float*)d_in[3],  *b1 = (const float*)d_in[4];
    const float* W2 = (const float*)d_in[5],  *b2 = (const float*)d_in[6];
    const float* W3 = (const float*)d_in[7],  *b3 = (const float*)d_in[8];
    const float* W4 = (const float*)d_in[9],  *b4 = (const float*)d_in[10];
    const float* Wl = (const float*)d_in[11], *bl = (const float*)d_in[12];
    float* out = (float*)d_out;

    const int* src = ei;
    const int* tgt = ei + Ee;

    int gemm_grid = (Nn + 63) / 64;
    int agg_grid  = (Nn * 16 + 255) / 256;

    k_zero <<<(Nn + 255) / 256, 256>>>();
    k_count<<<(Ee + 255) / 256, 256>>>(tgt);
    k_start<<<(Nn + 1023) / 1024, 1024>>>();
    k_fill <<<(Ee + 255) / 256, 256>>>(src, tgt);

    k_gemm<false><<<gemm_grid, 256>>>(x, W1, nullptr);
    k_agg<<<agg_grid, 256>>>();
    k_gemm<true><<<gemm_grid, 256>>>(nullptr, W2, b1);
    k_agg<<<agg_grid, 256>>>();
    k_gemm<true><<<gemm_grid, 256>>>(nullptr, W3, b2);
    k_agg<<<agg_grid, 256>>>();
    k_gemm<true><<<gemm_grid, 256>>>(nullptr, W4, b3);
    k_agg<<<agg_grid, 256>>>();

    k_pool<<<128, 256>>>(batch);
    k_final<<<1, Gg * Cc>>>(Wl, bl, b4, out);
}

// round 7
// speedup vs baseline: 1.0423x; 1.0423x over previous
#include <cuda_runtime.h>
#include <cuda_fp16.h>

#define Nn 100000
#define Ee 1600000
#define Hh 64
#define Cc 10
#define Gg 64

// ---------------- static device scratch (no allocations allowed) ----------------
__device__ int   d_counts[Nn];               // in-degree (excl. self loop)
__device__ int   d_cursor[Nn];               // placement cursors
__device__ int   d_start[Nn];                // CSR row start (permuted order, irrelevant)
__device__ float d_dinv[Nn];                 // rsqrt(1 + indeg)
__device__ int   d_sorted[Ee];               // src node id grouped by tgt
__device__ __align__(16) __half2 d_g16[Nn * 32];  // GEMM output in fp16: dinv[row]*(u@W), 128B/row
__device__ float d_h[Nn * Hh];               // aggregation output: dinv[t] * sum (fp32)
__device__ float d_psum[Gg * Hh];            // pooled sums
__device__ float d_pcnt[Gg];                 // per-graph node counts
__device__ int   d_gcnt;                     // global offset counter

// ---------------- prep kernels ----------------
__global__ void k_zero() {
    int i = blockIdx.x * blockDim.x + threadIdx.x;
    if (i < Nn) { d_counts[i] = 0; d_cursor[i] = 0; }
    if (i < Gg * Hh) d_psum[i] = 0.0f;
    if (i < Gg) d_pcnt[i] = 0.0f;
    if (i == 0) d_gcnt = 0;
}

// 4 edges/thread, int4 loads -> 4 independent atomics in flight (MLP=4)
__global__ void k_count(const int* __restrict__ tgt) {
    int e0 = 4 * (blockIdx.x * blockDim.x + threadIdx.x);
    if (e0 + 3 < Ee) {
        int4 t = *(const int4*)&tgt[e0];
        atomicAdd(&d_counts[t.x], 1);
        atomicAdd(&d_counts[t.y], 1);
        atomicAdd(&d_counts[t.z], 1);
        atomicAdd(&d_counts[t.w], 1);
    } else {
        for (int e = e0; e < Ee; e++) atomicAdd(&d_counts[tgt[e]], 1);
    }
}

// Block-aggregated offset allocation: start[i] = global_base + exclusive_prefix(counts)
__global__ void k_start() {
    int tid = threadIdx.x;
    int i = blockIdx.x * 1024 + tid;
    int v = (i < Nn) ? d_counts[i] : 0;
    int lane = tid & 31, wid = tid >> 5;
    int x = v;
#pragma unroll
    for (int d = 1; d < 32; d <<= 1) {
        int t = __shfl_up_sync(0xffffffffu, x, d);
        if (lane >= d) x += t;
    }
    __shared__ int ws[32];
    __shared__ int sbase;
    if (lane == 31) ws[wid] = x;
    __syncthreads();
    if (wid == 0) {
        int y = ws[lane];
#pragma unroll
        for (int d = 1; d < 32; d <<= 1) {
            int t = __shfl_up_sync(0xffffffffu, y, d);
            if (lane >= d) y += t;
        }
        ws[lane] = y;
    }
    __syncthreads();
    if (tid == 0) sbase = atomicAdd(&d_gcnt, ws[31]);
    __syncthreads();
    int excl = x - v + (wid ? ws[wid - 1] : 0);
    if (i < Nn) {
        d_start[i] = sbase + excl;
        d_dinv[i]  = rsqrtf(1.0f + (float)v);
    }
}

// 4 edges/thread, int4 loads -> 4 independent atomic+store chains (MLP=4)
__global__ void k_fill(const int* __restrict__ src, const int* __restrict__ tgt) {
    int e0 = 4 * (blockIdx.x * blockDim.x + threadIdx.x);
    if (e0 + 3 < Ee) {
        int4 t = *(const int4*)&tgt[e0];
        int4 s = *(const int4*)&src[e0];
        int p0 = d_start[t.x] + atomicAdd(&d_cursor[t.x], 1);
        int p1 = d_start[t.y] + atomicAdd(&d_cursor[t.y], 1);
        int p2 = d_start[t.z] + atomicAdd(&d_cursor[t.z], 1);
        int p3 = d_start[t.w] + atomicAdd(&d_cursor[t.w], 1);
        d_sorted[p0] = s.x;
        d_sorted[p1] = s.y;
        d_sorted[p2] = s.z;
        d_sorted[p3] = s.w;
    } else {
        for (int e = e0; e < Ee; e++) {
            int t = tgt[e];
            int pos = d_start[t] + atomicAdd(&d_cursor[t], 1);
            d_sorted[pos] = src[e];
        }
    }
}

// ---------------- fused GEMM: g16[row] = fp16( dinv[row] * (pre(in[row]) @ W) ) ----------------
// PRE=false: in = x.  PRE=true: in = d_h, pre(v) = relu(v + bprev).
template <bool PRE>
__global__ void __launch_bounds__(256) k_gemm(const float* __restrict__ xin,
                                              const float* __restrict__ W,
                                              const float* __restrict__ bprev) {
    __shared__ float Ws[64][64];
    __shared__ float inT[64][68];
    int tid = threadIdx.x;
    int row0 = blockIdx.x * 64;
    const float* in = PRE ? d_h : xin;

#pragma unroll
    for (int p = 0; p < 4; p++) {
        int f = tid + p * 256;
        int k = f >> 4, j = f & 15;
        float4 w = *(const float4*)&W[k * 64 + 4 * j];
        *(float4*)&Ws[k][4 * j] = w;
    }
#pragma unroll
    for (int p = 0; p < 4; p++) {
        int f = tid + p * 256;
        int r = f >> 4, j = f & 15;
        int row = row0 + r;
        float4 v = make_float4(0.f, 0.f, 0.f, 0.f);
        if (row < Nn) v = *(const float4*)&in[row * 64 + 4 * j];
        if (PRE) {
            v.x = fmaxf(v.x + bprev[4 * j + 0], 0.f);
            v.y = fmaxf(v.y + bprev[4 * j + 1], 0.f);
            v.z = fmaxf(v.z + bprev[4 * j + 2], 0.f);
            v.w = fmaxf(v.w + bprev[4 * j + 3], 0.f);
        }
        inT[4 * j + 0][r] = v.x;
        inT[4 * j + 1][r] = v.y;
        inT[4 * j + 2][r] = v.z;
        inT[4 * j + 3][r] = v.w;
    }
    __syncthreads();

    int ty = tid >> 4, tx = tid & 15;
    float acc[4][4] = {};
#pragma unroll 8
    for (int k = 0; k < 64; k++) {
        float4 a = *(float4*)&inT[k][4 * ty];
        float4 b = *(float4*)&Ws[k][4 * tx];
        float av[4] = {a.x, a.y, a.z, a.w};
        float bv[4] = {b.x, b.y, b.z, b.w};
#pragma unroll
        for (int i = 0; i < 4; i++)
#pragma unroll
            for (int j = 0; j < 4; j++)
                acc[i][j] = fmaf(av[i], bv[j], acc[i][j]);
    }
#pragma unroll
    for (int i = 0; i < 4; i++) {
        int row = row0 + 4 * ty + i;
        if (row < Nn) {
            float dv = d_dinv[row];
            __half2 p0 = __floats2half2_rn(acc[i][0] * dv, acc[i][1] * dv);
            __half2 p1 = __floats2half2_rn(acc[i][2] * dv, acc[i][3] * dv);
            uint2 pk = make_uint2(reinterpret_cast<const unsigned&>(p0),
                                  reinterpret_cast<const unsigned&>(p1));
            *(uint2*)&d_g16[row * 32 + 2 * tx] = pk;
        }
    }
}

// ---------------- aggregation: d_h[t] = dinv[t] * (g[t] + sum_{s in N(t)} g[s]) ----------------
// 8-lane group per node; each lane owns one 16B chunk (8 halves), fp32 accumulate.
__global__ void __launch_bounds__(256) k_agg() {
    int gid  = (blockIdx.x * blockDim.x + threadIdx.x) >> 3;
    int lane = threadIdx.x & 7;
    if (gid >= Nn) return;
    int t = gid;
    int base = d_start[t];
    int cnt  = d_counts[t];
    const float4* __restrict__ g = (const float4*)d_g16;  // 8 float4 per row

    float acc[8];
    {
        float4 r = g[t * 8 + lane];  // self loop
        const __half2* h = (const __half2*)&r;
#pragma unroll
        for (int k = 0; k < 4; k++) {
            float2 f = __half22float2(h[k]);
            acc[2 * k] = f.x; acc[2 * k + 1] = f.y;
        }
    }
    int i = 0;
    for (; i + 4 <= cnt; i += 4) {
        int s0 = d_sorted[base + i + 0];
        int s1 = d_sorted[base + i + 1];
        int s2 = d_sorted[base + i + 2];
        int s3 = d_sorted[base + i + 3];
        float4 r0 = g[s0 * 8 + lane];
        float4 r1 = g[s1 * 8 + lane];
        float4 r2 = g[s2 * 8 + lane];
        float4 r3 = g[s3 * 8 + lane];
        const __half2* h0 = (const __half2*)&r0;
        const __half2* h1 = (const __half2*)&r1;
        const __half2* h2 = (const __half2*)&r2;
        const __half2* h3 = (const __half2*)&r3;
#pragma unroll
        for (int k = 0; k < 4; k++) {
            float2 f0 = __half22float2(h0[k]);
            float2 f1 = __half22float2(h1[k]);
            float2 f2 = __half22float2(h2[k]);
            float2 f3 = __half22float2(h3[k]);
            acc[2 * k]     += (f0.x + f1.x) + (f2.x + f3.x);
            acc[2 * k + 1] += (f0.y + f1.y) + (f2.y + f3.y);
        }
    }
    for (; i < cnt; i++) {
        int s = d_sorted[base + i];
        float4 r = g[s * 8 + lane];
        const __half2* h = (const __half2*)&r;
#pragma unroll
        for (int k = 0; k < 4; k++) {
            float2 f = __half22float2(h[k]);
            acc[2 * k] += f.x; acc[2 * k + 1] += f.y;
        }
    }
    float dv = d_dinv[t];
    float4 o0 = make_float4(acc[0] * dv, acc[1] * dv, acc[2] * dv, acc[3] * dv);
    float4 o1 = make_float4(acc[4] * dv, acc[5] * dv, acc[6] * dv, acc[7] * dv);
    *(float4*)&d_h[t * 64 + 8 * lane]     = o0;
    *(float4*)&d_h[t * 64 + 8 * lane + 4] = o1;
}

// ---------------- mean pool (batch sorted; run-accumulate, flush on change) ----------------
__global__ void __launch_bounds__(256) k_pool(const int* __restrict__ batch) {
    int ngroups = gridDim.x * (blockDim.x >> 4);
    int gid  = (blockIdx.x * blockDim.x + threadIdx.x) >> 4;
    int lane = threadIdx.x & 15;
    int chunk = (Nn + ngroups - 1) / ngroups;
    int lo = gid * chunk;
    int hi = min(lo + chunk, Nn);
    float4 acc = make_float4(0.f, 0.f, 0.f, 0.f);
    int cur = -1, rc = 0;
    for (int n = lo; n < hi; n++) {
        int bg = batch[n];
        if (bg != cur) {
            if (cur >= 0) {
                atomicAdd(&d_psum[cur * 64 + 4 * lane + 0], acc.x);
                atomicAdd(&d_psum[cur * 64 + 4 * lane + 1], acc.y);
                atomicAdd(&d_psum[cur * 64 + 4 * lane + 2], acc.z);
                atomicAdd(&d_psum[cur * 64 + 4 * lane + 3], acc.w);
                if (lane == 0) atomicAdd(&d_pcnt[cur], (float)rc);
            }
            cur = bg; acc = make_float4(0.f, 0.f, 0.f, 0.f); rc = 0;
        }
        float4 v = *(const float4*)&d_h[n * 64 + 4 * lane];
        acc.x += v.x; acc.y += v.y; acc.z += v.z; acc.w += v.w;
        rc++;
    }
    if (cur >= 0) {
        atomicAdd(&d_psum[cur * 64 + 4 * lane + 0], acc.x);
        atomicAdd(&d_psum[cur * 64 + 4 * lane + 1], acc.y);
        atomicAdd(&d_psum[cur * 64 + 4 * lane + 2], acc.z);
        atomicAdd(&d_psum[cur * 64 + 4 * lane + 3], acc.w);
        if (lane == 0) atomicAdd(&d_pcnt[cur], (float)rc);
    }
}

// ---------------- head: out[g,c] = (psum[g]/cnt[g] + b4) @ Wl + bl ----------------
__global__ void k_final(const float* __restrict__ Wl, const float* __restrict__ bl,
                        const float* __restrict__ b4, float* __restrict__ out) {
    int tid = threadIdx.x;
    if (tid >= Gg * Cc) return;
    int gi = tid / Cc, c = tid % Cc;
    float inv = 1.0f / fmaxf(d_pcnt[gi], 1.0f);
    float acc = bl[c];
#pragma unroll 8
    for (int k = 0; k < 64; k++) {
        float pooled = d_psum[gi * 64 + k] * inv + b4[k];
        acc = fmaf(pooled, Wl[k * Cc + c], acc);
    }
    out[gi * Cc + c] = acc;
}

// ---------------- launch ----------------
extern "C" void kernel_launch(void* const* d_in, const int* in_sizes, int n_in,
                              void* d_out, int out_size) {
    const float* x     = (const float*)d_in[0];
    const int*   ei    = (const int*)d_in[1];     // int32 (JAX x64 disabled)
    const int*   batch = (const int*)d_in[2];
    const float* W1 = (const float*)d_in[3],  *b1 = (const float*)d_in[4];
    const float* W2 = (const float*)d_in[5],  *b2 = (const float*)d_in[6];
    const float* W3 = (const float*)d_in[7],  *b3 = (const float*)d_in[8];
    const float* W4 = (const float*)d_in[9],  *b4 = (const float*)d_in[10];
    const float* Wl = (const float*)d_in[11], *bl = (const float*)d_in[12];
    float* out = (float*)d_out;

    const int* src = ei;
    const int* tgt = ei + Ee;

    int gemm_grid = (Nn + 63) / 64;
    int agg_grid  = (Nn * 8 + 255) / 256;
    int edge4_grid = (Ee / 4 + 255) / 256;

    k_zero <<<(Nn + 255) / 256, 256>>>();
    k_count<<<edge4_grid, 256>>>(tgt);
    k_start<<<(Nn + 1023) / 1024, 1024>>>();
    k_fill <<<edge4_grid, 256>>>(src, tgt);

    k_gemm<false><<<gemm_grid, 256>>>(x, W1, nullptr);
    k_agg<<<agg_grid, 256>>>();
    k_gemm<true><<<gemm_grid, 256>>>(nullptr, W2, b1);
    k_agg<<<agg_grid, 256>>>();
    k_gemm<true><<<gemm_grid, 256>>>(nullptr, W3, b2);
    k_agg<<<agg_grid, 256>>>();
    k_gemm<true><<<gemm_grid, 256>>>(nullptr, W4, b3);
    k_agg<<<agg_grid, 256>>>();

    k_pool<<<128, 256>>>(batch);
    k_final<<<1, Gg * Cc>>>(Wl, bl, b4, out);
}